// round 10
// baseline (speedup 1.0000x reference)
#include <cuda_runtime.h>

typedef unsigned int u32;
typedef unsigned long long u64;

// ---- packed f32x2 helpers (Blackwell sm_103a) ------------------------------
__device__ __forceinline__ u64 pack2(float lo, float hi) {
    u64 r; asm("mov.b64 %0, {%1, %2};" : "=l"(r) : "f"(lo), "f"(hi)); return r;
}
__device__ __forceinline__ void unpack2(u64 v, float& lo, float& hi) {
    asm("mov.b64 {%0, %1}, %2;" : "=f"(lo), "=f"(hi) : "l"(v));
}
__device__ __forceinline__ void fma2(u64& d, u64 a, u64 b, u64 c) {
    asm("fma.rn.f32x2 %0, %1, %2, %3;" : "=l"(d) : "l"(a), "l"(b), "l"(c));
}

#define H2C 2654435761u
#define H3C 805459861u

// Weight port split by 4-col groups: groups 0..11 (cols 0..47) from the
// CONSTANT port (warp-uniform LDC only), groups 12..15 (cols 48..63) from
// smem. s2: groups 0..2 const, group 3 smem. Every weight load is shared by
// the thread's TWO points -> per-point weight traffic halves on both ports.
#define OFF_S1 0
#define OFF_S2 2048
#define OFF_C1 3072
#define OFF_C2 5120
#define OFF_C3 9216
#define W_TOTAL 9408
__constant__ __align__(16) float CW[W_TOTAL];
__device__   __align__(16) float WPACK[W_TOTAL];

__global__ void pack_weights(const float* __restrict__ s1,
                             const float* __restrict__ s2,
                             const float* __restrict__ c1,
                             const float* __restrict__ c2,
                             const float* __restrict__ c3) {
    int t = blockIdx.x * 256 + threadIdx.x;
    if (t >= W_TOTAL) return;
    float v;
    if      (t < OFF_S2) v = s1[t - OFF_S1];
    else if (t < OFF_C1) v = s2[t - OFF_S2];
    else if (t < OFF_C2) v = c1[t - OFF_C1];
    else if (t < OFF_C3) v = c2[t - OFF_C2];
    else                 v = c3[t - OFF_C3];
    WPACK[t] = v;
}

// res = ceil(16 * s^l), s = float32(2^0.4) (rounded up) => 65/257/1025 at
// l=5/10/15. MAX_DIRECT = 2. Gathers one point's 16 levels -> 32 features,
// either into a register array or a private smem column.
__device__ __forceinline__ void gather_point(float px, float py, float pz,
                                             const float* __restrict__ grids,
                                             float* encReg,        // if != 0
                                             float* bufCol)        // else STS
{
    const int RES_[16]  = {16,22,28,37,49,65,85,112,148,195,257,338,446,589,777,1025};
    const u32 SZ_[16]   = {4096u,10648u,21952u,50656u,117656u,274632u,
                           524288u,524288u,524288u,524288u,524288u,
                           524288u,524288u,524288u,524288u,524288u};
    #pragma unroll
    for (int l = 0; l < 16; l++) {
        const int R = RES_[l];
        const u32 S = SZ_[l];
        const float Rf = (float)R;
        float u = px * Rf, v = py * Rf, w = pz * Rf;
        float fu = floorf(u), fv = floorf(v), fw = floorf(w);
        float fx = u - fu, fy = v - fv, fz = w - fw;
        int ix = (int)fu, iy = (int)fv, iz = (int)fw;

        u32 idx[8];
        if (l <= 2) {
            #pragma unroll
            for (int j = 0; j < 8; j++) {
                int cx = ix + ((j >> 2) & 1);
                int cy = iy + ((j >> 1) & 1);
                int cz = iz + (j & 1);
                idx[j] = (u32)(cz * (R * R) + cy * R + cx) % S;
            }
        } else {
            u32 hx0 = (u32)ix;           u32 hx1 = hx0 + 1u;
            u32 hy0 = (u32)iy * H2C;     u32 hy1 = hy0 + H2C;
            u32 hz0 = (u32)iz * H3C;     u32 hz1 = hz0 + H3C;
            #pragma unroll
            for (int j = 0; j < 8; j++) {
                u32 h = ((j & 4) ? hx1 : hx0) ^ ((j & 2) ? hy1 : hy0) ^ ((j & 1) ? hz1 : hz0);
                idx[j] = (l >= 6) ? (h & 524287u) : (h % S);
            }
        }

        const float2* g = (const float2*)grids + (size_t)l * 524288u;
        float2 cc[8];
        #pragma unroll
        for (int j = 0; j < 8; j++) cc[j] = __ldg(g + idx[j]);

        const float gx = 1.f - fx, gy = 1.f - fy, gz = 1.f - fz;
        float c00x = cc[0].x*gx + cc[4].x*fx, c00y = cc[0].y*gx + cc[4].y*fx;
        float c01x = cc[1].x*gx + cc[5].x*fx, c01y = cc[1].y*gx + cc[5].y*fx;
        float c10x = cc[2].x*gx + cc[6].x*fx, c10y = cc[2].y*gx + cc[6].y*fx;
        float c11x = cc[3].x*gx + cc[7].x*fx, c11y = cc[3].y*gx + cc[7].y*fx;
        float c0x = c00x*gy + c10x*fy, c0y = c00y*gy + c10y*fy;
        float c1x = c01x*gy + c11x*fy, c1y = c01y*gy + c11y*fy;
        // NOTE: replicates reference bug: c0*(1-fz) + c1*fy   (fy, not fz!)
        float fex = c0x*gz + c1x*fy;
        float fey = c0y*gz + c1y*fy;
        if (encReg) { encReg[2*l] = fex; encReg[2*l+1] = fey; }
        else        { bufCol[(2*l)*128] = fex; bufCol[(2*l+1)*128] = fey; }
    }
}

// 2 points per thread (A register-resident, B via private smem column).
// 3 blocks/SM -> 168-reg budget: spills structurally impossible.
__global__ void __launch_bounds__(128, 3) nerf_fused(
    const float* __restrict__ xin,     // (N,19)
    const float* __restrict__ grids,   // (16, 524288, 2)
    const float* __restrict__ gw_s1,   // (32,64)
    const float* __restrict__ gw_s2,   // (64,16)
    const float* __restrict__ gw_c1,   // (32,64)
    const float* __restrict__ gw_c2,   // (64,64)
    float* __restrict__ out,           // (N,4)
    int N)
{
    extern __shared__ __align__(16) char smem_raw[];
    float*      BUF = (float*)smem_raw;                         // 64*128 fl = 32768B
    ulonglong2* W1s = (ulonglong2*)(smem_raw + 32768);          // 32*4  = 2048B
    ulonglong2* W3s = (ulonglong2*)(smem_raw + 34816);          // 32*4  = 2048B
    ulonglong2* W4s = (ulonglong2*)(smem_raw + 36864);          // 64*4  = 4096B
    ulonglong2* W2s = (ulonglong2*)(smem_raw + 40960);          // 64*1  = 1024B
    float*      sxd = (float*)(smem_raw + 41984);               // 256*17 fl = 17408B

    const int tid = threadIdx.x;
    {
        float* w1f = (float*)W1s;
        float* w3f = (float*)W3s;
        float* w4f = (float*)W4s;
        float* w2f = (float*)W2s;
        for (int t = tid; t < 512; t += 128) {        // 32 rows x 16 cols (48..63)
            int r = t >> 4, c = t & 15;
            w1f[t] = gw_s1[r * 64 + 48 + c];
            w3f[t] = gw_c1[r * 64 + 48 + c];
        }
        for (int t = tid; t < 1024; t += 128) {       // 64 rows x 16 cols (48..63)
            int r = t >> 4, c = t & 15;
            w4f[t] = gw_c2[r * 64 + 48 + c];
        }
        for (int t = tid; t < 256; t += 128) {        // 64 rows x 4 cols (12..15)
            int r = t >> 2, c = t & 3;
            w2f[t] = gw_s2[r * 16 + 12 + c];
        }
        // direc staging: sxd[p*17 + e] = x[(base_pt+p)*19 + 3 + e]
        const int basept = blockIdx.x * 256;
        for (int t = tid; t < 256 * 16; t += 128) {
            int p = t >> 4, e = t & 15;
            int pt = basept + p;
            sxd[p * 17 + e] = (pt < N) ? xin[(size_t)pt * 19 + 3 + e] : 0.f;
        }
    }
    __syncthreads();

    const int iA = blockIdx.x * 256 + tid;
    const int iB = iA + 128;
    const bool vA = iA < N, vB = iB < N;
    if (!vA) return;   // N multiple of 128; per-block all-or-nothing on A

    // ---- phase A: gathers (B -> smem column, A -> registers) ----------------
    {
        float pxB = 0.f, pyB = 0.f, pzB = 0.f;
        if (vB) {
            pxB = __ldg(xin + (size_t)iB * 19 + 0);
            pyB = __ldg(xin + (size_t)iB * 19 + 1);
            pzB = __ldg(xin + (size_t)iB * 19 + 2);
        }
        gather_point(pxB, pyB, pzB, grids, (float*)0, BUF + tid);
    }
    float encA[32];
    {
        float pxA = __ldg(xin + (size_t)iA * 19 + 0);
        float pyA = __ldg(xin + (size_t)iA * 19 + 1);
        float pzA = __ldg(xin + (size_t)iA * 19 + 2);
        gather_point(pxA, pyA, pzA, grids, encA, (float*)0);
    }

    const ulonglong2* W1c = (const ulonglong2*)(CW + OFF_S1);  // 16 u128/row
    const ulonglong2* W2c = (const ulonglong2*)(CW + OFF_S2);  // 4 u128/row
    const ulonglong2* W3c = (const ulonglong2*)(CW + OFF_C1);
    const ulonglong2* W4c = (const ulonglong2*)(CW + OFF_C2);

    // ---- phase B: gemm1 (32x64) col-halves, relu folded into gemm2 ----------
    // Half h: const groups 6h..6h+5 (cols 24h..24h+23), smem groups 2h..2h+1
    // (cols 48+8h..48+8h+7). Weight loads shared by A and B.
    u64 ovA8[8], ovB8[8];
    #pragma unroll
    for (int j = 0; j < 8; j++) { ovA8[j] = 0ull; ovB8[j] = 0ull; }

    #pragma unroll
    for (int h = 0; h < 2; h++) {
        u64 aaA[16], aaB[16];
        #pragma unroll
        for (int j = 0; j < 16; j++) { aaA[j] = 0ull; aaB[j] = 0ull; }
        #pragma unroll
        for (int k = 0; k < 32; k++) {
            u64 aA = pack2(encA[k], encA[k]);
            float eB = BUF[k * 128 + tid];
            u64 aB = pack2(eB, eB);
            #pragma unroll
            for (int u = 0; u < 6; u++) {
                ulonglong2 w = W1c[k*16 + 6*h + u];
                fma2(aaA[2*u],   aA, w.x, aaA[2*u]);
                fma2(aaA[2*u+1], aA, w.y, aaA[2*u+1]);
                fma2(aaB[2*u],   aB, w.x, aaB[2*u]);
                fma2(aaB[2*u+1], aB, w.y, aaB[2*u+1]);
            }
            #pragma unroll
            for (int v = 0; v < 2; v++) {
                ulonglong2 w = W1s[k*4 + 2*h + v];
                fma2(aaA[12+2*v],   aA, w.x, aaA[12+2*v]);
                fma2(aaA[12+2*v+1], aA, w.y, aaA[12+2*v+1]);
                fma2(aaB[12+2*v],   aB, w.x, aaB[12+2*v]);
                fma2(aaB[12+2*v+1], aB, w.y, aaB[12+2*v+1]);
            }
        }
        // fold: relu(h1 cols m,m+1) into gemm2 (64x16), shared weight loads
        #pragma unroll
        for (int t = 0; t < 16; t++) {
            int m = (t < 12) ? (24*h + 2*t) : (48 + 8*h + 2*(t - 12));
            float loA, hiA; unpack2(aaA[t], loA, hiA);
            float loB, hiB; unpack2(aaB[t], loB, hiB);
            loA = fmaxf(loA, 0.f); hiA = fmaxf(hiA, 0.f);
            loB = fmaxf(loB, 0.f); hiB = fmaxf(hiB, 0.f);
            u64 aloA = pack2(loA, loA), ahiA = pack2(hiA, hiA);
            u64 aloB = pack2(loB, loB), ahiB = pack2(hiB, hiB);
            #pragma unroll
            for (int j = 0; j < 3; j++) {
                ulonglong2 w0 = W2c[m*4 + j];
                ulonglong2 w1 = W2c[(m+1)*4 + j];
                fma2(ovA8[2*j],   aloA, w0.x, ovA8[2*j]);
                fma2(ovA8[2*j+1], aloA, w0.y, ovA8[2*j+1]);
                fma2(ovA8[2*j],   ahiA, w1.x, ovA8[2*j]);
                fma2(ovA8[2*j+1], ahiA, w1.y, ovA8[2*j+1]);
                fma2(ovB8[2*j],   aloB, w0.x, ovB8[2*j]);
                fma2(ovB8[2*j+1], aloB, w0.y, ovB8[2*j+1]);
                fma2(ovB8[2*j],   ahiB, w1.x, ovB8[2*j]);
                fma2(ovB8[2*j+1], ahiB, w1.y, ovB8[2*j+1]);
            }
            {
                ulonglong2 w0 = W2s[m];
                ulonglong2 w1 = W2s[m+1];
                fma2(ovA8[6], aloA, w0.x, ovA8[6]);
                fma2(ovA8[7], aloA, w0.y, ovA8[7]);
                fma2(ovA8[6], ahiA, w1.x, ovA8[6]);
                fma2(ovA8[7], ahiA, w1.y, ovA8[7]);
                fma2(ovB8[6], aloB, w0.x, ovB8[6]);
                fma2(ovB8[7], aloB, w0.y, ovB8[7]);
                fma2(ovB8[6], ahiB, w1.x, ovB8[6]);
                fma2(ovB8[7], ahiB, w1.y, ovB8[7]);
            }
        }
    }
    float ovA[16], ovB[16];
    #pragma unroll
    for (int t = 0; t < 8; t++) {
        unpack2(ovA8[t], ovA[2*t], ovA[2*t+1]);
        unpack2(ovB8[t], ovB[2*t], ovB[2*t+1]);
    }
    const float sigmaA = ovA[0], sigmaB = ovB[0];

    // ---- phase C: gemm3 (32x64) col-halves -> hcA regs / hcB smem ----------
    float hcA[64];
    #pragma unroll
    for (int h = 0; h < 2; h++) {
        u64 aaA[16], aaB[16];
        #pragma unroll
        for (int j = 0; j < 16; j++) { aaA[j] = 0ull; aaB[j] = 0ull; }
        #pragma unroll
        for (int k = 0; k < 32; k++) {
            float cA = (k < 16) ? sxd[tid*17 + k]         : ovA[k - 16];
            float cB = (k < 16) ? sxd[(128 + tid)*17 + k] : ovB[k - 16];
            u64 aA = pack2(cA, cA);
            u64 aB = pack2(cB, cB);
            #pragma unroll
            for (int u = 0; u < 6; u++) {
                ulonglong2 w = W3c[k*16 + 6*h + u];
                fma2(aaA[2*u],   aA, w.x, aaA[2*u]);
                fma2(aaA[2*u+1], aA, w.y, aaA[2*u+1]);
                fma2(aaB[2*u],   aB, w.x, aaB[2*u]);
                fma2(aaB[2*u+1], aB, w.y, aaB[2*u+1]);
            }
            #pragma unroll
            for (int v = 0; v < 2; v++) {
                ulonglong2 w = W3s[k*4 + 2*h + v];
                fma2(aaA[12+2*v],   aA, w.x, aaA[12+2*v]);
                fma2(aaA[12+2*v+1], aA, w.y, aaA[12+2*v+1]);
                fma2(aaB[12+2*v],   aB, w.x, aaB[12+2*v]);
                fma2(aaB[12+2*v+1], aB, w.y, aaB[12+2*v+1]);
            }
        }
        // relu -> hcA regs, hcB -> private smem column (enc region is dead)
        #pragma unroll
        for (int t = 0; t < 16; t++) {
            int m = (t < 12) ? (24*h + 2*t) : (48 + 8*h + 2*(t - 12));
            float loA, hiA; unpack2(aaA[t], loA, hiA);
            float loB, hiB; unpack2(aaB[t], loB, hiB);
            hcA[m]   = fmaxf(loA, 0.f);
            hcA[m+1] = fmaxf(hiA, 0.f);
            BUF[m*128 + tid]     = fmaxf(loB, 0.f);
            BUF[(m+1)*128 + tid] = fmaxf(hiB, 0.f);
        }
    }

    // ---- phase C2: gemm4 (64x64) col-halves + fused relu+gemm5 --------------
    float c0A = 0.f, c1A = 0.f, c2A = 0.f;
    float c0B = 0.f, c1B = 0.f, c2B = 0.f;
    #pragma unroll
    for (int h = 0; h < 2; h++) {
        u64 aaA[16], aaB[16];
        #pragma unroll
        for (int j = 0; j < 16; j++) { aaA[j] = 0ull; aaB[j] = 0ull; }
        #pragma unroll
        for (int k = 0; k < 64; k++) {
            u64 aA = pack2(hcA[k], hcA[k]);
            float hB = BUF[k*128 + tid];
            u64 aB = pack2(hB, hB);
            #pragma unroll
            for (int u = 0; u < 6; u++) {
                ulonglong2 w = W4c[k*16 + 6*h + u];
                fma2(aaA[2*u],   aA, w.x, aaA[2*u]);
                fma2(aaA[2*u+1], aA, w.y, aaA[2*u+1]);
                fma2(aaB[2*u],   aB, w.x, aaB[2*u]);
                fma2(aaB[2*u+1], aB, w.y, aaB[2*u+1]);
            }
            #pragma unroll
            for (int v = 0; v < 2; v++) {
                ulonglong2 w = W4s[k*4 + 2*h + v];
                fma2(aaA[12+2*v],   aA, w.x, aaA[12+2*v]);
                fma2(aaA[12+2*v+1], aA, w.y, aaA[12+2*v+1]);
                fma2(aaB[12+2*v],   aB, w.x, aaB[12+2*v]);
                fma2(aaB[12+2*v+1], aB, w.y, aaB[12+2*v+1]);
            }
        }
        // relu + gemm5 (64x3, const)
        #pragma unroll
        for (int t = 0; t < 16; t++) {
            int m = (t < 12) ? (24*h + 2*t) : (48 + 8*h + 2*(t - 12));
            float w0 = CW[OFF_C3 + m*3 + 0],     w1 = CW[OFF_C3 + m*3 + 1],     w2 = CW[OFF_C3 + m*3 + 2];
            float u0 = CW[OFF_C3 + (m+1)*3 + 0], u1 = CW[OFF_C3 + (m+1)*3 + 1], u2 = CW[OFF_C3 + (m+1)*3 + 2];
            float loA, hiA; unpack2(aaA[t], loA, hiA);
            loA = fmaxf(loA, 0.f); hiA = fmaxf(hiA, 0.f);
            c0A += loA * w0 + hiA * u0;
            c1A += loA * w1 + hiA * u1;
            c2A += loA * w2 + hiA * u2;
            float loB, hiB; unpack2(aaB[t], loB, hiB);
            loB = fmaxf(loB, 0.f); hiB = fmaxf(hiB, 0.f);
            c0B += loB * w0 + hiB * u0;
            c1B += loB * w1 + hiB * u1;
            c2B += loB * w2 + hiB * u2;
        }
    }

    // ---- phase D: sigmoid + store -------------------------------------------
    {
        float4 r;
        r.x = 1.f / (1.f + expf(-c0A));
        r.y = 1.f / (1.f + expf(-c1A));
        r.z = 1.f / (1.f + expf(-c2A));
        r.w = sigmaA;
        ((float4*)out)[iA] = r;
    }
    if (vB) {
        float4 r;
        r.x = 1.f / (1.f + expf(-c0B));
        r.y = 1.f / (1.f + expf(-c1B));
        r.z = 1.f / (1.f + expf(-c2B));
        r.w = sigmaB;
        ((float4*)out)[iB] = r;
    }
}

#define SMEM_BYTES (41984 + 17408)

extern "C" void kernel_launch(void* const* d_in, const int* in_sizes, int n_in,
                              void* d_out, int out_size) {
    const float* x     = (const float*)d_in[0];
    const float* grids = (const float*)d_in[1];
    const float* ws1   = (const float*)d_in[2];
    const float* ws2   = (const float*)d_in[3];
    const float* wc1   = (const float*)d_in[4];
    const float* wc2   = (const float*)d_in[5];
    const float* wc3   = (const float*)d_in[6];
    float* out = (float*)d_out;

    // pack all weights into one device buffer, then ONE memcpy node to const.
    pack_weights<<<(W_TOTAL + 255) / 256, 256>>>(ws1, ws2, wc1, wc2, wc3);
    void* wpack_ptr = nullptr;
    cudaGetSymbolAddress(&wpack_ptr, WPACK);
    cudaMemcpyToSymbolAsync(CW, wpack_ptr, W_TOTAL * sizeof(float), 0,
                            cudaMemcpyDeviceToDevice, 0);

    cudaFuncSetAttribute(nerf_fused, cudaFuncAttributeMaxDynamicSharedMemorySize,
                         SMEM_BYTES);

    const int N = in_sizes[0] / 19;
    const int blocks = (N + 255) / 256;   // 256 points per 128-thread block
    nerf_fused<<<blocks, 128, SMEM_BYTES>>>(x, grids, ws1, ws2, wc1, wc2, out, N);
}

// round 11
// speedup vs baseline: 1.9524x; 1.9524x over previous
#include <cuda_runtime.h>

typedef unsigned int u32;
typedef unsigned long long u64;

// ---- packed f32x2 helpers (Blackwell sm_103a) ------------------------------
__device__ __forceinline__ u64 pack2(float lo, float hi) {
    u64 r; asm("mov.b64 %0, {%1, %2};" : "=l"(r) : "f"(lo), "f"(hi)); return r;
}
__device__ __forceinline__ void unpack2(u64 v, float& lo, float& hi) {
    asm("mov.b64 {%0, %1}, %2;" : "=f"(lo), "=f"(hi) : "l"(v));
}
__device__ __forceinline__ void fma2(u64& d, u64 a, u64 b, u64 c) {
    asm("fma.rn.f32x2 %0, %1, %2, %3;" : "=l"(d) : "l"(a), "l"(b), "l"(c));
}

#define H2C 2654435761u
#define H3C 805459861u

// Calibrated dual-port weight split (f_smem = 0.44 optimum):
//   L1 cost  = 468k (gathers) + n_smem x 221 x 2.08 cyc
//   const    =                  n_const x 55.3 x 13.4 cyc / SMSP
// gemm1/3/4: lower 32 out-cols const, upper 32 smem (as R5).
// gemm2: ALL const (this is the R11 delta vs R5 - rebalances ports to ~939k).
// All LDC addresses warp-uniform (divergent LDC is catastrophic, R8).
#define OFF_S1 0
#define OFF_S2 2048
#define OFF_C1 3072
#define OFF_C2 5120
#define OFF_C3 9216
#define W_TOTAL 9408
__constant__ __align__(16) float CW[W_TOTAL];
__device__   __align__(16) float WPACK[W_TOTAL];

__global__ void pack_weights(const float* __restrict__ s1,
                             const float* __restrict__ s2,
                             const float* __restrict__ c1,
                             const float* __restrict__ c2,
                             const float* __restrict__ c3) {
    int t = blockIdx.x * 256 + threadIdx.x;
    if (t >= W_TOTAL) return;
    float v;
    if      (t < OFF_S2) v = s1[t - OFF_S1];
    else if (t < OFF_C1) v = s2[t - OFF_S2];
    else if (t < OFF_C2) v = c1[t - OFF_C1];
    else if (t < OFF_C3) v = c2[t - OFF_C2];
    else                 v = c3[t - OFF_C3];
    WPACK[t] = v;
}

__global__ void __launch_bounds__(128, 4) nerf_fused(
    const float* __restrict__ xin,     // (N,19)
    const float* __restrict__ grids,   // (16, 524288, 2)
    const float* __restrict__ gw_s1,   // (32,64)
    const float* __restrict__ gw_s2,   // (64,16)  (unused; gemm2 from const)
    const float* __restrict__ gw_c1,   // (32,64)
    const float* __restrict__ gw_c2,   // (64,64)
    float* __restrict__ out,           // (N,4)
    int N)
{
    __shared__ __align__(16) ulonglong2 W1s[32 * 8];  // s1 cols 32..63
    __shared__ __align__(16) ulonglong2 W3s[32 * 8];  // c1 cols 32..63
    __shared__ __align__(16) ulonglong2 W4s[64 * 8];  // c2 cols 32..63
    // xin staged: coalesced global loads, conflict-free LDS (19 coprime 32).
    __shared__ float sx[128 * 19];

    const int tid = threadIdx.x;
    {
        float* w1f = (float*)W1s;
        float* w3f = (float*)W3s;
        float* w4f = (float*)W4s;
        for (int t = tid; t < 1024; t += 128) {
            int r = t >> 5, c = t & 31;
            w1f[t] = gw_s1[r * 64 + 32 + c];
            w3f[t] = gw_c1[r * 64 + 32 + c];
        }
        for (int t = tid; t < 2048; t += 128) {
            int r = t >> 5, c = t & 31;
            w4f[t] = gw_c2[r * 64 + 32 + c];
        }
        const int base = blockIdx.x * (128 * 19);
        const int lim  = N * 19;
        #pragma unroll
        for (int t = tid; t < 128 * 19; t += 128) {
            int g = base + t;
            sx[t] = (g < lim) ? xin[g] : 0.f;
        }
    }
    __syncthreads();

    const int i = blockIdx.x * 128 + tid;
    if (i >= N) return;

    const float px = sx[tid * 19 + 0];
    const float py = sx[tid * 19 + 1];
    const float pz = sx[tid * 19 + 2];

    // res = ceil(16 * s^l), s = float32(2^0.4) (rounded up) => 65/257/1025 at l=5/10/15.
    const int RES_[16]  = {16,22,28,37,49,65,85,112,148,195,257,338,446,589,777,1025};
    const u32 SZ_[16]   = {4096u,10648u,21952u,50656u,117656u,274632u,
                           524288u,524288u,524288u,524288u,524288u,
                           524288u,524288u,524288u,524288u,524288u};
    // MAX_DIRECT = 2

    // gemm1 accumulators (enc @ w_sigma1), fused into the gather loop
    // (fusion provides the load-latency covering work - R9 showed explicit
    // prefetch does no better than this).
    u64 acc[32];
    #pragma unroll
    for (int j = 0; j < 32; j++) acc[j] = 0ull;

    const ulonglong2* W1c = (const ulonglong2*)(CW + OFF_S1);

    #pragma unroll
    for (int l = 0; l < 16; l++) {
        const int R = RES_[l];
        const u32 S = SZ_[l];
        const float Rf = (float)R;
        float u = px * Rf, v = py * Rf, w = pz * Rf;
        float fu = floorf(u), fv = floorf(v), fw = floorf(w);
        float fx = u - fu, fy = v - fv, fz = w - fw;
        int ix = (int)fu, iy = (int)fv, iz = (int)fw;

        u32 idx[8];
        if (l <= 2) {
            #pragma unroll
            for (int j = 0; j < 8; j++) {
                int cx = ix + ((j >> 2) & 1);
                int cy = iy + ((j >> 1) & 1);
                int cz = iz + (j & 1);
                idx[j] = (u32)(cz * (R * R) + cy * R + cx) % S;
            }
        } else {
            u32 hx0 = (u32)ix;           u32 hx1 = hx0 + 1u;
            u32 hy0 = (u32)iy * H2C;     u32 hy1 = hy0 + H2C;
            u32 hz0 = (u32)iz * H3C;     u32 hz1 = hz0 + H3C;
            #pragma unroll
            for (int j = 0; j < 8; j++) {
                u32 h = ((j & 4) ? hx1 : hx0) ^ ((j & 2) ? hy1 : hy0) ^ ((j & 1) ? hz1 : hz0);
                idx[j] = (l >= 6) ? (h & 524287u) : (h % S);
            }
        }

        const float2* g = (const float2*)grids + (size_t)l * 524288u;
        float2 cc[8];
        #pragma unroll
        for (int j = 0; j < 8; j++) cc[j] = __ldg(g + idx[j]);

        const float gx = 1.f - fx, gy = 1.f - fy, gz = 1.f - fz;
        float c00x = cc[0].x*gx + cc[4].x*fx, c00y = cc[0].y*gx + cc[4].y*fx;
        float c01x = cc[1].x*gx + cc[5].x*fx, c01y = cc[1].y*gx + cc[5].y*fx;
        float c10x = cc[2].x*gx + cc[6].x*fx, c10y = cc[2].y*gx + cc[6].y*fx;
        float c11x = cc[3].x*gx + cc[7].x*fx, c11y = cc[3].y*gx + cc[7].y*fx;
        float c0x = c00x*gy + c10x*fy, c0y = c00y*gy + c10y*fy;
        float c1x = c01x*gy + c11x*fy, c1y = c01y*gy + c11y*fy;
        // NOTE: replicates reference bug: c0*(1-fz) + c1*fy   (fy, not fz!)
        float fex = c0x*gz + c1x*fy;
        float fey = c0y*gz + c1y*fy;

        // gemm1 partial: k = 2l and 2l+1, dual-port
        u64 a0 = pack2(fex, fex);
        u64 a1 = pack2(fey, fey);
        #pragma unroll
        for (int j = 0; j < 8; j++) {
            ulonglong2 w0 = W1c[(2*l)   * 16 + j];    // cols 4j..4j+3
            ulonglong2 w1 = W1c[(2*l+1) * 16 + j];
            fma2(acc[2*j],   a0, w0.x, acc[2*j]);
            fma2(acc[2*j+1], a0, w0.y, acc[2*j+1]);
            fma2(acc[2*j],   a1, w1.x, acc[2*j]);
            fma2(acc[2*j+1], a1, w1.y, acc[2*j+1]);
            ulonglong2 s0 = W1s[(2*l)   * 8 + j];     // cols 32+4j..+3
            ulonglong2 s1v = W1s[(2*l+1) * 8 + j];
            fma2(acc[16+2*j],   a0, s0.x,  acc[16+2*j]);
            fma2(acc[16+2*j+1], a0, s0.y,  acc[16+2*j+1]);
            fma2(acc[16+2*j],   a1, s1v.x, acc[16+2*j]);
            fma2(acc[16+2*j+1], a1, s1v.y, acc[16+2*j+1]);
        }
    }

    // ---- relu(h1) folded into gemm2 (64x16), ALL const (R11 rebalance) ------
    u64 ovacc[8];
    #pragma unroll
    for (int j = 0; j < 8; j++) ovacc[j] = 0ull;
    const ulonglong2* W2c = (const ulonglong2*)(CW + OFF_S2);  // 4 u128/row

    #pragma unroll
    for (int q = 0; q < 32; q++) {
        float lo, hi; unpack2(acc[q], lo, hi);
        lo = fmaxf(lo, 0.f); hi = fmaxf(hi, 0.f);
        int m = 2*q;            // q<16: cols 2q; q>=16: cols 32+2(q-16) == 2q
        u64 alo = pack2(lo, lo), ahi = pack2(hi, hi);
        #pragma unroll
        for (int j = 0; j < 4; j++) {
            ulonglong2 w0 = W2c[m*4 + j];            // out cols 4j..4j+3
            ulonglong2 w1 = W2c[(m+1)*4 + j];
            fma2(ovacc[2*j],   alo, w0.x, ovacc[2*j]);
            fma2(ovacc[2*j+1], alo, w0.y, ovacc[2*j+1]);
            fma2(ovacc[2*j],   ahi, w1.x, ovacc[2*j]);
            fma2(ovacc[2*j+1], ahi, w1.y, ovacc[2*j+1]);
        }
    }
    float ov[16];
    #pragma unroll
    for (int j = 0; j < 8; j++) unpack2(ovacc[j], ov[2*j], ov[2*j+1]);
    const float sigma = ov[0];

    // ---- gemm3 (32x64), dual-port -------------------------------------------
    u64 acc3[32];
    #pragma unroll
    for (int j = 0; j < 32; j++) acc3[j] = 0ull;
    const ulonglong2* W3c = (const ulonglong2*)(CW + OFF_C1);
    const ulonglong2* W4c = (const ulonglong2*)(CW + OFF_C2);

    #pragma unroll
    for (int k = 0; k < 32; k++) {
        float cik = (k < 16) ? sx[tid*19 + 3 + k] : ov[k - 16];
        u64 a = pack2(cik, cik);
        #pragma unroll
        for (int j = 0; j < 8; j++) {
            ulonglong2 wc = W3c[k*16 + j];        // cols 4j..4j+3
            fma2(acc3[2*j],   a, wc.x, acc3[2*j]);
            fma2(acc3[2*j+1], a, wc.y, acc3[2*j+1]);
            ulonglong2 ws = W3s[k*8 + j];         // cols 32+4j..+3
            fma2(acc3[16+2*j],   a, ws.x, acc3[16+2*j]);
            fma2(acc3[16+2*j+1], a, ws.y, acc3[16+2*j+1]);
        }
    }

    // ---- relu(hc) streamed into gemm4 (64x64), dual-port --------------------
    u64 a4[32];
    #pragma unroll
    for (int j = 0; j < 32; j++) a4[j] = 0ull;
    #pragma unroll
    for (int q = 0; q < 32; q++) {
        float lo, hi; unpack2(acc3[q], lo, hi);
        lo = fmaxf(lo, 0.f); hi = fmaxf(hi, 0.f);
        int m = 2*q;
        u64 alo = pack2(lo, lo), ahi = pack2(hi, hi);
        #pragma unroll
        for (int j = 0; j < 8; j++) {
            ulonglong2 w0 = W4c[m*16 + j];
            ulonglong2 w1 = W4c[(m+1)*16 + j];
            fma2(a4[2*j],   alo, w0.x, a4[2*j]);
            fma2(a4[2*j+1], alo, w0.y, a4[2*j+1]);
            fma2(a4[2*j],   ahi, w1.x, a4[2*j]);
            fma2(a4[2*j+1], ahi, w1.y, a4[2*j+1]);
            ulonglong2 s0 = W4s[m*8 + j];
            ulonglong2 s1v = W4s[(m+1)*8 + j];
            fma2(a4[16+2*j],   alo, s0.x,  a4[16+2*j]);
            fma2(a4[16+2*j+1], alo, s0.y,  a4[16+2*j+1]);
            fma2(a4[16+2*j],   ahi, s1v.x, a4[16+2*j]);
            fma2(a4[16+2*j+1], ahi, s1v.y, a4[16+2*j+1]);
        }
    }

    // ---- relu + gemm5 (64x3, const) + sigmoid -------------------------------
    float col0 = 0.f, col1 = 0.f, col2 = 0.f;
    #pragma unroll
    for (int q = 0; q < 32; q++) {
        float lo, hi; unpack2(a4[q], lo, hi);
        lo = fmaxf(lo, 0.f); hi = fmaxf(hi, 0.f);
        int m = 2*q;
        col0 += lo * CW[OFF_C3 + m*3 + 0] + hi * CW[OFF_C3 + (m+1)*3 + 0];
        col1 += lo * CW[OFF_C3 + m*3 + 1] + hi * CW[OFF_C3 + (m+1)*3 + 1];
        col2 += lo * CW[OFF_C3 + m*3 + 2] + hi * CW[OFF_C3 + (m+1)*3 + 2];
    }

    col0 = 1.f / (1.f + expf(-col0));
    col1 = 1.f / (1.f + expf(-col1));
    col2 = 1.f / (1.f + expf(-col2));

    float4 r; r.x = col0; r.y = col1; r.z = col2; r.w = sigma;
    ((float4*)out)[i] = r;
}

extern "C" void kernel_launch(void* const* d_in, const int* in_sizes, int n_in,
                              void* d_out, int out_size) {
    const float* x     = (const float*)d_in[0];
    const float* grids = (const float*)d_in[1];
    const float* ws1   = (const float*)d_in[2];
    const float* ws2   = (const float*)d_in[3];
    const float* wc1   = (const float*)d_in[4];
    const float* wc2   = (const float*)d_in[5];
    const float* wc3   = (const float*)d_in[6];
    float* out = (float*)d_out;

    // pack all weights into one device buffer, then ONE memcpy node to const.
    pack_weights<<<(W_TOTAL + 255) / 256, 256>>>(ws1, ws2, wc1, wc2, wc3);
    void* wpack_ptr = nullptr;
    cudaGetSymbolAddress(&wpack_ptr, WPACK);
    cudaMemcpyToSymbolAsync(CW, wpack_ptr, W_TOTAL * sizeof(float), 0,
                            cudaMemcpyDeviceToDevice, 0);

    const int N = in_sizes[0] / 19;
    const int blocks = (N + 127) / 128;
    nerf_fused<<<blocks, 128>>>(x, grids, ws1, ws2, wc1, wc2, out, N);
}